// round 2
// baseline (speedup 1.0000x reference)
#include <cuda_runtime.h>
#include <mma.h>
#include <cstdint>

using namespace nvcuda;

// Problem constants
constexpr int Bb    = 4;
constexpr int NQ    = 2048;
constexpr int NK    = 1024;
constexpr int DQ    = 1024;
constexpr int DC    = 768;
constexpr int H     = 16;
constexpr int DH    = 64;
constexpr int INNER = 1024;   // H*DH

// Scratch (no cudaMalloc allowed)
__device__ float g_q  [(size_t)Bb * NQ * INNER];
__device__ float g_k  [(size_t)Bb * NK * INNER];
__device__ float g_v  [(size_t)Bb * NK * INNER];
__device__ float g_att[(size_t)Bb * NQ * INNER];

// ---------------------------------------------------------------------------
// Generic TF32 WMMA GEMM:  C[M,N] = A[M,K] @ B[K,N] (+ bias[N] if non-null)
// Block tile 64x64, BK=32, 4 warps (each 32x32 = 2x2 of 16x16x8 tf32 frags).
// ---------------------------------------------------------------------------
__global__ void __launch_bounds__(128)
gemm_tf32_kernel(const float* __restrict__ A, const float* __restrict__ Bmat,
                 const float* __restrict__ bias, float* __restrict__ C,
                 int M, int N, int K)
{
    __shared__ float As[64][36];   // ld 36 (x4B=144, 16B-aligned rows)
    __shared__ float Bs[32][68];
    __shared__ float Cs[64][68];

    const int m0 = blockIdx.y * 64;
    const int n0 = blockIdx.x * 64;
    const int t  = threadIdx.x;
    const int w  = t >> 5;
    const int wm = (w >> 1) * 32;  // warp row offset
    const int wn = (w & 1) * 32;   // warp col offset

    wmma::fragment<wmma::accumulator, 16, 16, 8, float> acc[2][2];
#pragma unroll
    for (int i = 0; i < 2; i++)
#pragma unroll
        for (int j = 0; j < 2; j++) wmma::fill_fragment(acc[i][j], 0.f);

    for (int kt = 0; kt < K; kt += 32) {
        // Load A tile 64x32 (512 float4, 4 per thread)
#pragma unroll
        for (int i = 0; i < 4; i++) {
            int f = t + i * 128;
            int r = f >> 3, c4 = f & 7;
            float4 v = *(const float4*)(A + (size_t)(m0 + r) * K + kt + c4 * 4);
            *(float4*)(&As[r][c4 * 4]) = v;
        }
        // Load B tile 32x64
#pragma unroll
        for (int i = 0; i < 4; i++) {
            int f = t + i * 128;
            int r = f >> 4, c4 = f & 15;
            float4 v = *(const float4*)(Bmat + (size_t)(kt + r) * N + n0 + c4 * 4);
            *(float4*)(&Bs[r][c4 * 4]) = v;
        }
        __syncthreads();

#pragma unroll
        for (int ks = 0; ks < 32; ks += 8) {
            wmma::fragment<wmma::matrix_a, 16, 16, 8, wmma::precision::tf32, wmma::row_major> af[2];
            wmma::fragment<wmma::matrix_b, 16, 16, 8, wmma::precision::tf32, wmma::row_major> bf[2];
#pragma unroll
            for (int i = 0; i < 2; i++) {
                wmma::load_matrix_sync(af[i], &As[wm + i * 16][ks], 36);
#pragma unroll
                for (int e = 0; e < af[i].num_elements; e++)
                    af[i].x[e] = wmma::__float_to_tf32(af[i].x[e]);
            }
#pragma unroll
            for (int j = 0; j < 2; j++) {
                wmma::load_matrix_sync(bf[j], &Bs[ks][wn + j * 16], 68);
#pragma unroll
                for (int e = 0; e < bf[j].num_elements; e++)
                    bf[j].x[e] = wmma::__float_to_tf32(bf[j].x[e]);
            }
#pragma unroll
            for (int i = 0; i < 2; i++)
#pragma unroll
                for (int j = 0; j < 2; j++)
                    wmma::mma_sync(acc[i][j], af[i], bf[j], acc[i][j]);
        }
        __syncthreads();
    }

    // Epilogue through smem (bias add)
#pragma unroll
    for (int i = 0; i < 2; i++)
#pragma unroll
        for (int j = 0; j < 2; j++)
            wmma::store_matrix_sync(&Cs[wm + i * 16][wn + j * 16], acc[i][j], 68,
                                    wmma::mem_row_major);
    __syncthreads();
#pragma unroll
    for (int i = 0; i < 32; i++) {
        int f = t + i * 128;
        int r = f >> 6, c = f & 63;
        float v = Cs[r][c] + (bias ? bias[n0 + c] : 0.f);
        C[(size_t)(m0 + r) * N + n0 + c] = v;
    }
}

// ---------------------------------------------------------------------------
// Attention kernel: one block = 32 queries of one (b,h).
// Full score row S[32][1024] in dynamic smem -> exact single-pass softmax.
// QK^T and PV via TF32 WMMA. 128 threads / 4 warps.
// Warp layout for a 32x64 output: mi = w&1 (16-row tile), nj = (w>>1)*2 (two
// 16-col tiles per warp).
// ---------------------------------------------------------------------------
__global__ void __launch_bounds__(128)
attn_kernel()
{
    extern __shared__ float sm[];
    float* S   = sm;                      // [32][1024]
    float* Qs  = sm + 32 * 1024;          // [32][68]
    float* KVs = Qs + 32 * 68;            // [64][68]

    const int bh = blockIdx.y;
    const int b  = bh / H;
    const int h  = bh % H;
    const int q0 = blockIdx.x * 32;
    const int t    = threadIdx.x;
    const int w    = t >> 5;
    const int lane = t & 31;
    const int mi = w & 1;          // 16-row tile index
    const int nj = (w >> 1) * 2;   // first of two 16-col tiles

    // ---- Load Q tile [32,64], pre-scaled by 1/sqrt(dh) ----
    const float* Qg = g_q + ((size_t)b * NQ + q0) * INNER + h * DH;
#pragma unroll
    for (int i = 0; i < 4; i++) {
        int f = t + i * 128;           // 512 float4
        int r = f >> 4, c4 = f & 15;
        float4 v = *(const float4*)(Qg + (size_t)r * INNER + c4 * 4);
        v.x *= 0.125f; v.y *= 0.125f; v.z *= 0.125f; v.w *= 0.125f;
        *(float4*)(&Qs[r * 68 + c4 * 4]) = v;
    }

    // ---- S = Q @ K^T over all 16 key tiles ----
    for (int kt = 0; kt < NK; kt += 64) {
        __syncthreads();   // prior users of KVs done (first iter: Q load visible too)
        const float* Kg = g_k + ((size_t)b * NK + kt) * INNER + h * DH;
#pragma unroll
        for (int i = 0; i < 8; i++) {
            int f = t + i * 128;       // 1024 float4
            int r = f >> 4, c4 = f & 15;
            *(float4*)(&KVs[r * 68 + c4 * 4]) =
                *(const float4*)(Kg + (size_t)r * INNER + c4 * 4);
        }
        __syncthreads();

        wmma::fragment<wmma::accumulator, 16, 16, 8, float> sacc[2];
        wmma::fill_fragment(sacc[0], 0.f);
        wmma::fill_fragment(sacc[1], 0.f);
#pragma unroll
        for (int ks = 0; ks < 64; ks += 8) {
            wmma::fragment<wmma::matrix_a, 16, 16, 8, wmma::precision::tf32, wmma::row_major> af;
            wmma::load_matrix_sync(af, &Qs[mi * 16 * 68 + ks], 68);
#pragma unroll
            for (int e = 0; e < af.num_elements; e++)
                af.x[e] = wmma::__float_to_tf32(af.x[e]);
#pragma unroll
            for (int j = 0; j < 2; j++) {
                // B(k,n) = K[n][k]: col_major view of KVs
                wmma::fragment<wmma::matrix_b, 16, 16, 8, wmma::precision::tf32, wmma::col_major> bf;
                wmma::load_matrix_sync(bf, &KVs[(nj + j) * 16 * 68 + ks], 68);
#pragma unroll
                for (int e = 0; e < bf.num_elements; e++)
                    bf.x[e] = wmma::__float_to_tf32(bf.x[e]);
                wmma::mma_sync(sacc[j], af, bf, sacc[j]);
            }
        }
#pragma unroll
        for (int j = 0; j < 2; j++)
            wmma::store_matrix_sync(&S[mi * 16 * 1024 + kt + (nj + j) * 16],
                                    sacc[j], 1024, wmma::mem_row_major);
    }
    __syncthreads();

    // ---- Exact softmax, one warp per 8 rows, lane-strided (conflict-free) ----
    for (int r = w * 8; r < w * 8 + 8; r++) {
        float* row = S + (size_t)r * 1024;
        float mx = -1e30f;
        for (int c = lane; c < 1024; c += 32) mx = fmaxf(mx, row[c]);
#pragma unroll
        for (int o = 16; o; o >>= 1) mx = fmaxf(mx, __shfl_xor_sync(0xffffffffu, mx, o));
        float s = 0.f;
        for (int c = lane; c < 1024; c += 32) { float e = __expf(row[c] - mx); row[c] = e; s += e; }
#pragma unroll
        for (int o = 16; o; o >>= 1) s += __shfl_xor_sync(0xffffffffu, s, o);
        float inv = 1.f / s;
        for (int c = lane; c < 1024; c += 32) row[c] *= inv;
    }

    // ---- O = P @ V, accumulators persist across all key tiles ----
    wmma::fragment<wmma::accumulator, 16, 16, 8, float> oacc[2];
    wmma::fill_fragment(oacc[0], 0.f);
    wmma::fill_fragment(oacc[1], 0.f);
    for (int kt = 0; kt < NK; kt += 64) {
        __syncthreads();   // prior KVs use done (first iter: softmax writes to S visible)
        const float* Vg = g_v + ((size_t)b * NK + kt) * INNER + h * DH;
#pragma unroll
        for (int i = 0; i < 8; i++) {
            int f = t + i * 128;
            int r = f >> 4, c4 = f & 15;
            *(float4*)(&KVs[r * 68 + c4 * 4]) =
                *(const float4*)(Vg + (size_t)r * INNER + c4 * 4);
        }
        __syncthreads();
#pragma unroll
        for (int ks = 0; ks < 64; ks += 8) {
            wmma::fragment<wmma::matrix_a, 16, 16, 8, wmma::precision::tf32, wmma::row_major> af;
            wmma::load_matrix_sync(af, &S[mi * 16 * 1024 + kt + ks], 1024);
#pragma unroll
            for (int e = 0; e < af.num_elements; e++)
                af.x[e] = wmma::__float_to_tf32(af.x[e]);
#pragma unroll
            for (int j = 0; j < 2; j++) {
                wmma::fragment<wmma::matrix_b, 16, 16, 8, wmma::precision::tf32, wmma::row_major> bf;
                wmma::load_matrix_sync(bf, &KVs[ks * 68 + (nj + j) * 16], 68);
#pragma unroll
                for (int e = 0; e < bf.num_elements; e++)
                    bf.x[e] = wmma::__float_to_tf32(bf.x[e]);
                wmma::mma_sync(oacc[j], af, bf, oacc[j]);
            }
        }
    }

    // ---- Store O tile to g_att [B, NQ, INNER] at head column ----
    float* Og = g_att + ((size_t)b * NQ + q0) * INNER + h * DH;
#pragma unroll
    for (int j = 0; j < 2; j++)
        wmma::store_matrix_sync(Og + (size_t)mi * 16 * INNER + (nj + j) * 16,
                                oacc[j], INNER, wmma::mem_row_major);
}

// ---------------------------------------------------------------------------
// Launch
// ---------------------------------------------------------------------------
extern "C" void kernel_launch(void* const* d_in, const int* in_sizes, int n_in,
                              void* d_out, int out_size)
{
    const float* x   = (const float*)d_in[0];   // [B,NQ,DQ]
    const float* ctx = (const float*)d_in[1];   // [B,NK,DC]
    const float* Wq  = (const float*)d_in[2];   // [DQ,INNER]
    const float* Wk  = (const float*)d_in[3];   // [DC,INNER]
    const float* Wv  = (const float*)d_in[4];   // [DC,INNER]
    const float* Wo  = (const float*)d_in[5];   // [INNER,DQ]
    const float* bo  = (const float*)d_in[6];   // [DQ]
    float* out = (float*)d_out;

    float *q, *k, *v, *att;
    cudaGetSymbolAddress((void**)&q,   g_q);
    cudaGetSymbolAddress((void**)&k,   g_k);
    cudaGetSymbolAddress((void**)&v,   g_v);
    cudaGetSymbolAddress((void**)&att, g_att);

    const int attn_smem = (32 * 1024 + 32 * 68 + 64 * 68) * (int)sizeof(float);
    cudaFuncSetAttribute(attn_kernel, cudaFuncAttributeMaxDynamicSharedMemorySize,
                         attn_smem);

    // Q = x @ Wq        [8192,1024] = [8192,1024]@[1024,1024]
    gemm_tf32_kernel<<<dim3(INNER / 64, (Bb * NQ) / 64), 128>>>(
        x, Wq, nullptr, q, Bb * NQ, INNER, DQ);
    // K = ctx @ Wk      [4096,1024] = [4096,768]@[768,1024]
    gemm_tf32_kernel<<<dim3(INNER / 64, (Bb * NK) / 64), 128>>>(
        ctx, Wk, nullptr, k, Bb * NK, INNER, DC);
    // V = ctx @ Wv
    gemm_tf32_kernel<<<dim3(INNER / 64, (Bb * NK) / 64), 128>>>(
        ctx, Wv, nullptr, v, Bb * NK, INNER, DC);
    // Attention: grid (q-tiles, b*h)
    attn_kernel<<<dim3(NQ / 32, Bb * H), 128, attn_smem>>>();
    // out = att @ Wo + bo
    gemm_tf32_kernel<<<dim3(DQ / 64, (Bb * NQ) / 64), 128>>>(
        att, Wo, bo, out, Bb * NQ, DQ, INNER);
}